// round 6
// baseline (speedup 1.0000x reference)
#include <cuda_runtime.h>
#include <cstdint>

#define EPS   1e-9f
#define ITERS 20
#define LDK   68      // padded shared row stride in floats (17 float4)

typedef unsigned long long ull;

__device__ __forceinline__ ull pack2f(float lo, float hi) {
    ull r; asm("mov.b64 %0, {%1, %2};" : "=l"(r) : "f"(lo), "f"(hi)); return r;
}
__device__ __forceinline__ void unpack2f(ull p, float& lo, float& hi) {
    asm("mov.b64 {%0, %1}, %2;" : "=f"(lo), "=f"(hi) : "l"(p));
}
// packed 2xfp32 FMA / ADD — only reachable via PTX on sm_10x
__device__ __forceinline__ ull ffma2(ull a, ull b, ull c) {
    ull d; asm("fma.rn.f32x2 %0, %1, %2, %3;" : "=l"(d) : "l"(a), "l"(b), "l"(c)); return d;
}
__device__ __forceinline__ ull fadd2(ull a, ull b) {
    ull d; asm("add.rn.f32x2 %0, %1, %2;" : "=l"(d) : "l"(a), "l"(b)); return d;
}

// dot(A, w): A = 32 packed f32x2 (one 64-float row/col in registers),
// w = 64-float broadcast vector in shared. 4 independent FMA chains of
// depth 8 (vs. the old single depth-32 chain), 16 broadcast LDS.128.
__device__ __forceinline__ float dot64(const ull* A, const float* w)
{
    ull a0 = 0, a1 = 0, a2 = 0, a3 = 0;
    const float4* w4 = reinterpret_cast<const float4*>(w);
    #pragma unroll
    for (int j = 0; j < 4; j++) {
        float4 t0 = w4[4 * j + 0];
        float4 t1 = w4[4 * j + 1];
        float4 t2 = w4[4 * j + 2];
        float4 t3 = w4[4 * j + 3];
        a0 = ffma2(A[8 * j + 0], pack2f(t0.x, t0.y), a0);
        a1 = ffma2(A[8 * j + 1], pack2f(t0.z, t0.w), a1);
        a2 = ffma2(A[8 * j + 2], pack2f(t1.x, t1.y), a2);
        a3 = ffma2(A[8 * j + 3], pack2f(t1.z, t1.w), a3);
        a0 = ffma2(A[8 * j + 4], pack2f(t2.x, t2.y), a0);
        a1 = ffma2(A[8 * j + 5], pack2f(t2.z, t2.w), a1);
        a2 = ffma2(A[8 * j + 6], pack2f(t3.x, t3.y), a2);
        a3 = ffma2(A[8 * j + 7], pack2f(t3.z, t3.w), a3);
    }
    ull s = fadd2(fadd2(a0, a1), fadd2(a2, a3));
    float l, h; unpack2f(s, l, h);
    return l + h;
}

__global__ __launch_bounds__(64)
void sinkhorn_kernel(const float* __restrict__ x, float* __restrict__ out)
{
    __shared__ __align__(16) float shK[64 * LDK];
    __shared__ __align__(16) float shv[64];
    __shared__ __align__(16) float shu[64];

    const int tid = threadIdx.x;
    const long long m = blockIdx.x;
    const float4* __restrict__ x4 = reinterpret_cast<const float4*>(x) + m * 1024;
    float4* __restrict__ o4       = reinterpret_cast<float4*>(out)     + m * 1024;

    // ---- coalesced load, exp, stage into padded shared -------------------
    #pragma unroll
    for (int j = 0; j < 16; j++) {
        int e4 = j * 64 + tid;            // float4 linear index within matrix
        float4 t = x4[e4];
        int row = e4 >> 4;
        int c4  = e4 & 15;
        float4 e;
        e.x = __expf(t.x); e.y = __expf(t.y);
        e.z = __expf(t.z); e.w = __expf(t.w);
        reinterpret_cast<float4*>(shK)[row * 17 + c4] = e;
    }
    shv[tid] = 1.0f;
    __syncthreads();

    // ---- gather row tid and column tid of K into packed registers --------
    ull kr[32];   // K[tid][0..63] as 32 float2
    ull kc[32];   // K[0..63][tid] as 32 float2 (pairs of rows)
    #pragma unroll
    for (int j = 0; j < 16; j++) {
        float4 t = reinterpret_cast<const float4*>(shK)[tid * 17 + j];
        kr[2 * j]     = pack2f(t.x, t.y);
        kr[2 * j + 1] = pack2f(t.z, t.w);
    }
    #pragma unroll
    for (int j = 0; j < 32; j++) {
        kc[j] = pack2f(shK[(2 * j) * LDK + tid], shK[(2 * j + 1) * LDK + tid]);
    }

    float u = 1.0f, v = 1.0f;

    #pragma unroll 1
    for (int it = 0; it < ITERS; it++) {
        // row step: u' = u / (u * (K v) + eps)   — all 64 threads, 1 row each
        float dot = dot64(kr, shv);
        u = __fdividef(u, fmaf(u, dot, EPS));
        shu[tid] = u;
        __syncthreads();

        // col step: v' = v / (v * (K^T u') + eps) — all 64 threads, 1 col each
        float cs = dot64(kc, shu);
        v = __fdividef(v, fmaf(v, cs, EPS));
        shv[tid] = v;
        __syncthreads();
    }

    // ---- output M = diag(u) K diag(v), staged through shared for coalescing
    #pragma unroll
    for (int j = 0; j < 16; j++) {
        float4 vv = reinterpret_cast<const float4*>(shv)[j];
        float k0, k1, k2, k3;
        unpack2f(kr[2 * j],     k0, k1);
        unpack2f(kr[2 * j + 1], k2, k3);
        float4 r;
        r.x = u * k0 * vv.x; r.y = u * k1 * vv.y;
        r.z = u * k2 * vv.z; r.w = u * k3 * vv.w;
        reinterpret_cast<float4*>(shK)[tid * 17 + j] = r;
    }
    __syncthreads();
    #pragma unroll
    for (int j = 0; j < 16; j++) {
        int e4 = j * 64 + tid;
        int row = e4 >> 4;
        int c4  = e4 & 15;
        o4[e4] = reinterpret_cast<const float4*>(shK)[row * 17 + c4];
    }
}

extern "C" void kernel_launch(void* const* d_in, const int* in_sizes, int n_in,
                              void* d_out, int out_size)
{
    const float* x = (const float*)d_in[0];
    float* out = (float*)d_out;
    int nmat = in_sizes[0] / 4096;   // 64*64 elements per matrix

    // Max shared-memory carveout so ~13 blocks (17.4KB each) fit per SM
    // instead of ~5-6 under the default L1-biased split.
    cudaFuncSetAttribute(sinkhorn_kernel,
                         cudaFuncAttributePreferredSharedMemoryCarveout, 100);

    sinkhorn_kernel<<<nmat, 64>>>(x, out);
}

// round 8
// speedup vs baseline: 1.0924x; 1.0924x over previous
#include <cuda_runtime.h>
#include <cstdint>

#define EPS   1e-9f
#define ITERS 20
#define LDK   68      // padded shared row stride in floats (17 float4)
#define VOFF  36      // float offset of second vector half (144B: 16B-aligned, bank-shift 4)

typedef unsigned long long ull;

__device__ __forceinline__ ull pack2f(float lo, float hi) {
    ull r; asm("mov.b64 %0, {%1, %2};" : "=l"(r) : "f"(lo), "f"(hi)); return r;
}
__device__ __forceinline__ void unpack2f(ull p, float& lo, float& hi) {
    asm("mov.b64 {%0, %1}, %2;" : "=f"(lo), "=f"(hi) : "l"(p));
}
// packed 2xfp32 FMA / ADD — only reachable via PTX on sm_10x
__device__ __forceinline__ ull ffma2(ull a, ull b, ull c) {
    ull d; asm("fma.rn.f32x2 %0, %1, %2, %3;" : "=l"(d) : "l"(a), "l"(b), "l"(c)); return d;
}
__device__ __forceinline__ ull fadd2(ull a, ull b) {
    ull d; asm("add.rn.f32x2 %0, %1, %2;" : "=l"(d) : "l"(a), "l"(b)); return d;
}

// Half-dot: 32-float segment held in 16 packed f32x2 regs vs. a 32-float
// vector half in shared. 8 broadcast LDS.128, 2 chains of depth 8,
// load->use interleaved (R2 style; the up-front-batched variant regressed).
__device__ __forceinline__ float halfdot(const ull* A, const float4* wh)
{
    ull a0 = 0, a1 = 0;
    #pragma unroll
    for (int j = 0; j < 8; j++) {
        float4 t = wh[j];
        a0 = ffma2(A[2 * j],     pack2f(t.x, t.y), a0);
        a1 = ffma2(A[2 * j + 1], pack2f(t.z, t.w), a1);
    }
    ull s = fadd2(a0, a1);
    float lo, hi; unpack2f(s, lo, hi);
    return lo + hi;
}

__global__ __launch_bounds__(128, 4)
void sinkhorn_kernel(const float* __restrict__ x, float* __restrict__ out)
{
    __shared__ __align__(16) float shK[64 * LDK];
    __shared__ __align__(16) float shv[72];
    __shared__ __align__(16) float shu[72];

    const int tid  = threadIdx.x;
    const int lane = tid & 31;
    const int warp = tid >> 5;
    const int sub  = lane & 15;       // position within half-group
    const int h    = lane >> 4;       // which half of the row/col (0 or 1)
    const int r    = warp * 16 + sub; // this thread's row (and col) index

    const long long m = blockIdx.x;
    const float4* __restrict__ x4 = reinterpret_cast<const float4*>(x) + m * 1024;
    float4* __restrict__ o4       = reinterpret_cast<float4*>(out)     + m * 1024;
    float4* shK4 = reinterpret_cast<float4*>(shK);

    // ---- coalesced load, exp, stage into padded shared -------------------
    #pragma unroll
    for (int j = 0; j < 8; j++) {
        int e4 = j * 128 + tid;           // float4 linear index within matrix
        float4 t = x4[e4];
        int row = e4 >> 4;
        int c4  = e4 & 15;
        float4 e;
        e.x = __expf(t.x); e.y = __expf(t.y);
        e.z = __expf(t.z); e.w = __expf(t.w);
        shK4[row * 17 + c4] = e;
    }
    if (tid < 72) shv[tid] = 1.0f;        // fills both halves (+ padding, harmless)
    __syncthreads();

    // ---- gather: half-row K[r, 32h..32h+31] and half-col K[32h..32h+31, r]
    ull kr[16], kc[16];                   // 64 registers of K data total
    #pragma unroll
    for (int j = 0; j < 8; j++) {
        float4 t = shK4[r * 17 + h * 8 + j];
        kr[2 * j]     = pack2f(t.x, t.y);
        kr[2 * j + 1] = pack2f(t.z, t.w);
    }
    #pragma unroll
    for (int j = 0; j < 16; j++) {
        kc[j] = pack2f(shK[(h * 32 + 2 * j) * LDK + r],
                       shK[(h * 32 + 2 * j + 1) * LDK + r]);
    }

    const float4* vh = reinterpret_cast<const float4*>(shv + h * VOFF);
    const float4* uh = reinterpret_cast<const float4*>(shu + h * VOFF);
    const int voff = (r & 31) + ((r >> 5) ? VOFF : 0);  // slot of value r in shu/shv

    float u = 1.0f, v = 1.0f;

    #pragma unroll 1
    for (int it = 0; it < ITERS; it++) {
        // row step: dot = K[r,:].v  (two half-dots joined by shfl.xor 16)
        float part = halfdot(kr, vh);
        float dot  = part + __shfl_xor_sync(0xffffffffu, part, 16);
        u = __fdividef(u, fmaf(u, dot, EPS));        // both halves compute identical u
        if (h == 0) shu[voff] = u;
        __syncthreads();

        // col step: cs = K[:,r].u'
        float cpart = halfdot(kc, uh);
        float cs    = cpart + __shfl_xor_sync(0xffffffffu, cpart, 16);
        v = __fdividef(v, fmaf(v, cs, EPS));
        if (h == 0) shv[voff] = v;
        __syncthreads();
    }

    // ---- output M = diag(u) K diag(v): scale this thread's half-row ------
    #pragma unroll
    for (int j = 0; j < 8; j++) {
        float4 t = vh[j];
        float k0, k1, k2, k3;
        unpack2f(kr[2 * j],     k0, k1);
        unpack2f(kr[2 * j + 1], k2, k3);
        float4 o;
        o.x = u * k0 * t.x; o.y = u * k1 * t.y;
        o.z = u * k2 * t.z; o.w = u * k3 * t.w;
        shK4[r * 17 + h * 8 + j] = o;
    }
    __syncthreads();

    // ---- coalesced copy-out ---------------------------------------------
    #pragma unroll
    for (int j = 0; j < 8; j++) {
        int e4 = j * 128 + tid;
        int row = e4 >> 4;
        int c4  = e4 & 15;
        o4[e4] = shK4[row * 17 + c4];
    }
}

extern "C" void kernel_launch(void* const* d_in, const int* in_sizes, int n_in,
                              void* d_out, int out_size)
{
    const float* x = (const float*)d_in[0];
    float* out = (float*)d_out;
    int nmat = in_sizes[0] / 4096;   // 64*64 elements per matrix
    sinkhorn_kernel<<<nmat, 128>>>(x, out);
}